// round 1
// baseline (speedup 1.0000x reference)
#include <cuda_runtime.h>
#include <math.h>

// Problem shape (fixed by dataset): B=32, T=1024, J=1024, H=2048
#define BB 32
#define TT 1024
#define JJ 1024
#define HH 2048
#define MM (BB*TT)   // 32768 rows

// ---------------- scratch ----------------
__device__ float g_h[(size_t)MM * HH];   // pre-activation buffer (largest layer)
__device__ float g_s[(size_t)MM * HH];   // spike buffer
__device__ float g_mu[HH];
__device__ float g_var[HH];

// ---------------- fp32 GEMM: C[M,N] = A[M,K] * B[N,K]^T ----------------
#define BM 128
#define BN 128
#define BKK 16

__global__ __launch_bounds__(256, 2) void sgemm_nt(
    const float* __restrict__ A, const float* __restrict__ B,
    float* __restrict__ C, int M, int N, int K)
{
    __shared__ float As[BKK][BM + 4];
    __shared__ float Bs[BKK][BN + 4];

    const int tid = threadIdx.x;
    const int tx = tid & 15;          // 0..15 -> N direction
    const int ty = tid >> 4;          // 0..15 -> M direction
    const int bm = blockIdx.y * BM;
    const int bn = blockIdx.x * BN;

    const int lrow = tid >> 2;        // 0..63
    const int lcol = (tid & 3) << 2;  // 0,4,8,12

    float acc[8][8];
#pragma unroll
    for (int i = 0; i < 8; i++)
#pragma unroll
        for (int j = 0; j < 8; j++) acc[i][j] = 0.0f;

    const float* Aptr = A + (size_t)bm * K;
    const float* Bptr = B + (size_t)bn * K;

    for (int k0 = 0; k0 < K; k0 += BKK) {
#pragma unroll
        for (int i = 0; i < 2; i++) {
            int r = lrow + i * 64;
            float4 va = *(const float4*)(Aptr + (size_t)r * K + k0 + lcol);
            As[lcol + 0][r] = va.x; As[lcol + 1][r] = va.y;
            As[lcol + 2][r] = va.z; As[lcol + 3][r] = va.w;
            float4 vb = *(const float4*)(Bptr + (size_t)r * K + k0 + lcol);
            Bs[lcol + 0][r] = vb.x; Bs[lcol + 1][r] = vb.y;
            Bs[lcol + 2][r] = vb.z; Bs[lcol + 3][r] = vb.w;
        }
        __syncthreads();

#pragma unroll
        for (int k = 0; k < BKK; k++) {
            float a[8], b[8];
#pragma unroll
            for (int i = 0; i < 8; i++) a[i] = As[k][ty * 8 + i];
#pragma unroll
            for (int j = 0; j < 8; j++) b[j] = Bs[k][tx * 8 + j];
#pragma unroll
            for (int i = 0; i < 8; i++)
#pragma unroll
                for (int j = 0; j < 8; j++)
                    acc[i][j] = fmaf(a[i], b[j], acc[i][j]);
        }
        __syncthreads();
    }

#pragma unroll
    for (int i = 0; i < 8; i++) {
        float* cp = C + (size_t)(bm + ty * 8 + i) * N + bn + tx * 8;
        float4 v0 = make_float4(acc[i][0], acc[i][1], acc[i][2], acc[i][3]);
        float4 v1 = make_float4(acc[i][4], acc[i][5], acc[i][6], acc[i][7]);
        *(float4*)(cp) = v0;
        *(float4*)(cp + 4) = v1;
    }
}

// ---------------- per-channel stats (mean, biased var) over 32768 rows ----------------
// block (32,16): 32 channels per block, 16-way row partition, double accumulators
__global__ void colstats(const float* __restrict__ h, int rows, int I)
{
    const int tx = threadIdx.x;
    const int ty = threadIdx.y;
    const int i = blockIdx.x * 32 + tx;

    double s = 0.0, q = 0.0;
    for (int r = ty; r < rows; r += 16) {
        double v = (double)h[(size_t)r * I + i];
        s += v;
        q += v * v;
    }

    __shared__ double sh_s[16][33];
    __shared__ double sh_q[16][33];
    sh_s[ty][tx] = s;
    sh_q[ty][tx] = q;
    __syncthreads();

    for (int off = 8; off > 0; off >>= 1) {
        if (ty < off) {
            sh_s[ty][tx] += sh_s[ty + off][tx];
            sh_q[ty][tx] += sh_q[ty + off][tx];
        }
        __syncthreads();
    }

    if (ty == 0) {
        double inv = 1.0 / (double)rows;
        double mu = sh_s[0][tx] * inv;
        double var = sh_q[0][tx] * inv - mu * mu;
        g_mu[i]  = (float)mu;
        g_var[i] = (float)var;
    }
}

// ---------------- BatchNorm + LIF scan (sequential in T per (b,i)) ----------------
__global__ void lif_scan(const float* __restrict__ h,
                         const float* __restrict__ gamma,
                         const float* __restrict__ bias,
                         const float* __restrict__ betap,
                         const float* __restrict__ U0,
                         float* __restrict__ S,
                         int Bn, int T, int I)
{
    int idx = blockIdx.x * blockDim.x + threadIdx.x;  // b*I + i
    if (idx >= Bn * I) return;
    int b = idx / I;
    int i = idx - b * I;

    float m = g_mu[i];
    float rstd = (float)(1.0 / sqrt((double)g_var[i] + 1e-5));
    float g  = gamma[i];
    float bi = bias[i];
    float beta = (float)(1.0 / (1.0 + exp(-(double)betap[i])));
    float ombeta = 1.0f - beta;

    float U = U0[idx];
    float Sv = 0.0f;

    const float* hp = h + (size_t)b * T * I + i;
    float* sp = S + (size_t)b * T * I + i;

    for (int t = 0; t < T; t++) {
        float x = ((hp[(size_t)t * I] - m) * rstd) * g + bi;
        U = beta * (U - Sv) + ombeta * x;          // soft reset, THETA = 1
        Sv = (U >= 1.0f) ? 1.0f : 0.0f;
        sp[(size_t)t * I] = Sv;
    }
}

// ---------------- driver ----------------
extern "C" void kernel_launch(void* const* d_in, const int* in_sizes, int n_in,
                              void* d_out, int out_size)
{
    const float* x      = (const float*)d_in[0];
    const float* W1     = (const float*)d_in[1];
    const float* beta1  = (const float*)d_in[2];
    const float* gamma1 = (const float*)d_in[3];
    const float* bias1  = (const float*)d_in[4];
    const float* U01    = (const float*)d_in[5];
    const float* W2     = (const float*)d_in[6];
    const float* beta2  = (const float*)d_in[7];
    const float* gamma2 = (const float*)d_in[8];
    const float* bias2  = (const float*)d_in[9];
    const float* U02    = (const float*)d_in[10];
    const float* W3     = (const float*)d_in[11];
    const float* beta3  = (const float*)d_in[12];
    const float* gamma3 = (const float*)d_in[13];
    const float* bias3  = (const float*)d_in[14];
    const float* U03    = (const float*)d_in[15];
    float* out = (float*)d_out;

    float *h, *s;
    cudaGetSymbolAddress((void**)&h, g_h);
    cudaGetSymbolAddress((void**)&s, g_s);

    // ---- layer 1: [M,J] x [H,J]^T -> [M,H] ----
    sgemm_nt<<<dim3(HH / BN, MM / BM), 256>>>(x, W1, h, MM, HH, JJ);
    colstats<<<HH / 32, dim3(32, 16)>>>(h, MM, HH);
    lif_scan<<<(BB * HH + 255) / 256, 256>>>(h, gamma1, bias1, beta1, U01, s, BB, TT, HH);

    // ---- layer 2: [M,H] x [H,H]^T -> [M,H] ----
    sgemm_nt<<<dim3(HH / BN, MM / BM), 256>>>(s, W2, h, MM, HH, HH);
    colstats<<<HH / 32, dim3(32, 16)>>>(h, MM, HH);
    lif_scan<<<(BB * HH + 255) / 256, 256>>>(h, gamma2, bias2, beta2, U02, s, BB, TT, HH);

    // ---- layer 3: [M,H] x [J,H]^T -> [M,J] ----
    sgemm_nt<<<dim3(JJ / BN, MM / BM), 256>>>(s, W3, h, MM, JJ, HH);
    colstats<<<JJ / 32, dim3(32, 16)>>>(h, MM, JJ);
    lif_scan<<<(BB * JJ + 255) / 256, 256>>>(h, gamma3, bias3, beta3, U03, out, BB, TT, JJ);
}

// round 3
// speedup vs baseline: 2.1521x; 2.1521x over previous
#include <cuda_runtime.h>
#include <cuda_fp16.h>
#include <math.h>
#include <stdint.h>

// Shapes fixed by dataset: B=32, T=1024, J=1024, H=2048
#define BB 32
#define TT 1024
#define JJ 1024
#define HH 2048
#define MM (BB*TT)   // 32768

// ---------------- scratch (device globals; no allocations allowed) ----------------
__device__ float  g_h [(size_t)MM * HH];      // pre-activation fp32 (256MB)
__device__ __half g_s16[(size_t)MM * HH];     // spikes fp16 (128MB)
__device__ __half g_x0[(size_t)MM * JJ];      // x hi
__device__ __half g_x1[(size_t)MM * JJ];      // x lo
__device__ __half g_w1a[(size_t)HH * JJ], g_w1b[(size_t)HH * JJ];
__device__ __half g_w2a[(size_t)HH * HH], g_w2b[(size_t)HH * HH];
__device__ __half g_w3a[(size_t)JJ * HH], g_w3b[(size_t)JJ * HH];
__device__ float  g_mu[HH], g_var[HH];

// ---------------- fp32 -> (hi, lo) fp16 split ----------------
__global__ void split_f32(const float* __restrict__ src,
                          __half* __restrict__ a, __half* __restrict__ b, size_t n)
{
    size_t i = (size_t)blockIdx.x * blockDim.x + threadIdx.x;
    if (i >= n) return;
    float v = src[i];
    __half hi = __float2half_rn(v);
    a[i] = hi;
    b[i] = __float2half_rn(v - __half2float(hi));
}

// ---------------- fp16 tensor-core GEMM: C[M,N] (+)= A[M,K] * (B0+B1)[N,K]^T ----------------
// block tile 128x128, k-tile 32, 8 warps (2x4), warp tile 64x32, double-buffered cp.async
#define GBM 128
#define GBN 128
#define GBK 32
#define TS  40                   // halves per smem row (32 + 8 pad = 80B, ldmatrix conflict-free)
#define TILE_H (128*TS)          // halves per tile

__device__ __forceinline__ void cpasync16(void* dst, const void* src) {
    unsigned sa = (unsigned)__cvta_generic_to_shared(dst);
    asm volatile("cp.async.cg.shared.global [%0], [%1], 16;\n" :: "r"(sa), "l"(src));
}
__device__ __forceinline__ void ldm4(uint32_t* r, const __half* p) {
    unsigned a = (unsigned)__cvta_generic_to_shared(p);
    asm volatile("ldmatrix.sync.aligned.m8n8.x4.shared.b16 {%0,%1,%2,%3}, [%4];"
                 : "=r"(r[0]), "=r"(r[1]), "=r"(r[2]), "=r"(r[3]) : "r"(a));
}
__device__ __forceinline__ void mma16816(float* c, const uint32_t* a, uint32_t b0, uint32_t b1) {
    asm volatile("mma.sync.aligned.m16n8k16.row.col.f32.f16.f16.f32 "
                 "{%0,%1,%2,%3},{%4,%5,%6,%7},{%8,%9},{%0,%1,%2,%3};"
                 : "+f"(c[0]), "+f"(c[1]), "+f"(c[2]), "+f"(c[3])
                 : "r"(a[0]), "r"(a[1]), "r"(a[2]), "r"(a[3]), "r"(b0), "r"(b1));
}

__global__ __launch_bounds__(256, 2) void gemm_fp16x2(
    const __half* __restrict__ A, const __half* __restrict__ B0, const __half* __restrict__ B1,
    float* __restrict__ C, int M, int N, int K, int accum)
{
    extern __shared__ __half smem[];
    __half* sA  = smem;                 // [2][TILE_H]
    __half* sB0 = smem + 2 * TILE_H;    // [2][TILE_H]
    __half* sB1 = smem + 4 * TILE_H;    // [2][TILE_H]

    const int tid  = threadIdx.x;
    const int lane = tid & 31;
    const int warp = tid >> 5;
    const int wm   = warp >> 2;   // 0..1
    const int wn   = warp & 3;    // 0..3
    const int bm   = blockIdx.y * GBM;
    const int bn   = blockIdx.x * GBN;

    const __half* Ag  = A  + (size_t)bm * K;
    const __half* B0g = B0 + (size_t)bn * K;
    const __half* B1g = B1 + (size_t)bn * K;

    float acc[4][4][4];
#pragma unroll
    for (int i = 0; i < 4; i++)
#pragma unroll
        for (int j = 0; j < 4; j++)
#pragma unroll
            for (int k = 0; k < 4; k++) acc[i][j][k] = 0.0f;

    const int NK = K / GBK;

    // stage loader: 512 16B-chunks per tile, 2 per thread per tile
    auto load_stage = [&](int kt, int st) {
        int kb = kt * GBK;
#pragma unroll
        for (int c = tid; c < 512; c += 256) {
            int r = c >> 2, q = c & 3;         // row, 16B chunk
            int so = st * TILE_H + r * TS + q * 8;
            size_t go = (size_t)r * K + kb + q * 8;
            cpasync16(sA  + so, Ag  + go);
            cpasync16(sB0 + so, B0g + go);
            cpasync16(sB1 + so, B1g + go);
        }
    };

    load_stage(0, 0);
    asm volatile("cp.async.commit_group;");

    for (int kt = 0; kt < NK; kt++) {
        const int st = kt & 1;
        if (kt + 1 < NK) {
            load_stage(kt + 1, st ^ 1);
            asm volatile("cp.async.commit_group;");
            asm volatile("cp.async.wait_group 1;");
        } else {
            asm volatile("cp.async.wait_group 0;");
        }
        __syncthreads();

        const __half* tA  = sA  + st * TILE_H;
        const __half* tB0 = sB0 + st * TILE_H;
        const __half* tB1 = sB1 + st * TILE_H;

#pragma unroll
        for (int k16 = 0; k16 < GBK; k16 += 16) {
            // A fragments: 4 m16 tiles
            uint32_t af[4][4];
            {
                int r  = wm * 64 + (lane & 7) + ((lane >> 3) & 1) * 8;
                int kc = k16 + (lane >> 4) * 8;
#pragma unroll
                for (int mt = 0; mt < 4; mt++)
                    ldm4(af[mt], tA + (r + mt * 16) * TS + kc);
            }
            // B parts
#pragma unroll
            for (int p = 0; p < 2; p++) {
                const __half* tB = p ? tB1 : tB0;
                uint32_t bf[2][4];
                {
                    int r  = wn * 32 + (lane & 7) + (lane >> 4) * 8;
                    int kc = k16 + ((lane >> 3) & 1) * 8;
#pragma unroll
                    for (int g = 0; g < 2; g++)
                        ldm4(bf[g], tB + (r + g * 16) * TS + kc);
                }
#pragma unroll
                for (int mt = 0; mt < 4; mt++)
#pragma unroll
                    for (int nt = 0; nt < 4; nt++)
                        mma16816(acc[mt][nt], af[mt], bf[nt >> 1][(nt & 1) * 2], bf[nt >> 1][(nt & 1) * 2 + 1]);
            }
        }
        __syncthreads();
    }

    // epilogue
#pragma unroll
    for (int mt = 0; mt < 4; mt++) {
#pragma unroll
        for (int nt = 0; nt < 4; nt++) {
            int row = bm + wm * 64 + mt * 16 + (lane >> 2);
            int col = bn + wn * 32 + nt * 8 + (lane & 3) * 2;
            float2* p0 = (float2*)(C + (size_t)row * N + col);
            float2* p1 = (float2*)(C + (size_t)(row + 8) * N + col);
            float2 v0 = make_float2(acc[mt][nt][0], acc[mt][nt][1]);
            float2 v1 = make_float2(acc[mt][nt][2], acc[mt][nt][3]);
            if (accum) {
                float2 o0 = *p0, o1 = *p1;
                v0.x += o0.x; v0.y += o0.y; v1.x += o1.x; v1.y += o1.y;
            }
            *p0 = v0; *p1 = v1;
        }
    }
}

// ---------------- per-channel stats over 32768 rows (double accumulators) ----------------
__global__ void colstats(const float* __restrict__ h, int rows, int I)
{
    const int tx = threadIdx.x, ty = threadIdx.y;
    const int i = blockIdx.x * 32 + tx;

    double s = 0.0, q = 0.0;
    for (int r = ty; r < rows; r += 16) {
        double v = (double)h[(size_t)r * I + i];
        s += v; q += v * v;
    }
    __shared__ double sh_s[16][33], sh_q[16][33];
    sh_s[ty][tx] = s; sh_q[ty][tx] = q;
    __syncthreads();
    for (int off = 8; off > 0; off >>= 1) {
        if (ty < off) { sh_s[ty][tx] += sh_s[ty+off][tx]; sh_q[ty][tx] += sh_q[ty+off][tx]; }
        __syncthreads();
    }
    if (ty == 0) {
        double inv = 1.0 / (double)rows;
        double mu = sh_s[0][tx] * inv;
        g_mu[i]  = (float)mu;
        g_var[i] = (float)(sh_q[0][tx] * inv - mu * mu);
    }
}

// ---------------- BatchNorm + LIF scan ----------------
template <typename OutT>
__global__ void lif_scan(const float* __restrict__ h,
                         const float* __restrict__ gamma, const float* __restrict__ bias,
                         const float* __restrict__ betap, const float* __restrict__ U0,
                         OutT* __restrict__ S, int Bn, int T, int I)
{
    int idx = blockIdx.x * blockDim.x + threadIdx.x;
    if (idx >= Bn * I) return;
    int b = idx / I, i = idx - b * I;

    float m = g_mu[i];
    float rstd = (float)(1.0 / sqrt((double)g_var[i] + 1e-5));
    float g = gamma[i], bi = bias[i];
    float beta = (float)(1.0 / (1.0 + exp(-(double)betap[i])));
    float ombeta = 1.0f - beta;

    float U = U0[idx], Sv = 0.0f;
    const float* hp = h + (size_t)b * T * I + i;
    OutT* sp = S + (size_t)b * T * I + i;

    for (int t = 0; t < T; t++) {
        float x = ((hp[(size_t)t * I] - m) * rstd) * g + bi;
        U = beta * (U - Sv) + ombeta * x;
        Sv = (U >= 1.0f) ? 1.0f : 0.0f;
        sp[(size_t)t * I] = (OutT)Sv;
    }
}

// ---------------- driver ----------------
extern "C" void kernel_launch(void* const* d_in, const int* in_sizes, int n_in,
                              void* d_out, int out_size)
{
    const float* x      = (const float*)d_in[0];
    const float* W1     = (const float*)d_in[1];
    const float* beta1  = (const float*)d_in[2];
    const float* gamma1 = (const float*)d_in[3];
    const float* bias1  = (const float*)d_in[4];
    const float* U01    = (const float*)d_in[5];
    const float* W2     = (const float*)d_in[6];
    const float* beta2  = (const float*)d_in[7];
    const float* gamma2 = (const float*)d_in[8];
    const float* bias2  = (const float*)d_in[9];
    const float* U02    = (const float*)d_in[10];
    const float* W3     = (const float*)d_in[11];
    const float* beta3  = (const float*)d_in[12];
    const float* gamma3 = (const float*)d_in[13];
    const float* bias3  = (const float*)d_in[14];
    const float* U03    = (const float*)d_in[15];
    float* out = (float*)d_out;

    float *h; __half *s16, *x0, *x1, *w1a, *w1b, *w2a, *w2b, *w3a, *w3b;
    cudaGetSymbolAddress((void**)&h,   g_h);
    cudaGetSymbolAddress((void**)&s16, g_s16);
    cudaGetSymbolAddress((void**)&x0,  g_x0);
    cudaGetSymbolAddress((void**)&x1,  g_x1);
    cudaGetSymbolAddress((void**)&w1a, g_w1a);
    cudaGetSymbolAddress((void**)&w1b, g_w1b);
    cudaGetSymbolAddress((void**)&w2a, g_w2a);
    cudaGetSymbolAddress((void**)&w2b, g_w2b);
    cudaGetSymbolAddress((void**)&w3a, g_w3a);
    cudaGetSymbolAddress((void**)&w3b, g_w3b);

    cudaFuncSetAttribute(gemm_fp16x2, cudaFuncAttributeMaxDynamicSharedMemorySize, 6 * TILE_H * 2);
    const size_t SMEMB = 6 * TILE_H * 2;

    // splits
    split_f32<<<(unsigned)(((size_t)MM * JJ + 255) / 256), 256>>>(x,  x0,  x1,  (size_t)MM * JJ);
    split_f32<<<(unsigned)(((size_t)HH * JJ + 255) / 256), 256>>>(W1, w1a, w1b, (size_t)HH * JJ);
    split_f32<<<(unsigned)(((size_t)HH * HH + 255) / 256), 256>>>(W2, w2a, w2b, (size_t)HH * HH);
    split_f32<<<(unsigned)(((size_t)JJ * HH + 255) / 256), 256>>>(W3, w3a, w3b, (size_t)JJ * HH);

    // ---- layer 1: h = (x0+x1) @ (W1a+W1b)^T ----
    gemm_fp16x2<<<dim3(HH / GBN, MM / GBM), 256, SMEMB>>>(x0, w1a, w1b, h, MM, HH, JJ, 0);
    gemm_fp16x2<<<dim3(HH / GBN, MM / GBM), 256, SMEMB>>>(x1, w1a, w1b, h, MM, HH, JJ, 1);
    colstats<<<HH / 32, dim3(32, 16)>>>(h, MM, HH);
    lif_scan<__half><<<(BB * HH + 255) / 256, 256>>>(h, gamma1, bias1, beta1, U01, s16, BB, TT, HH);

    // ---- layer 2 ----
    gemm_fp16x2<<<dim3(HH / GBN, MM / GBM), 256, SMEMB>>>(s16, w2a, w2b, h, MM, HH, HH, 0);
    colstats<<<HH / 32, dim3(32, 16)>>>(h, MM, HH);
    lif_scan<__half><<<(BB * HH + 255) / 256, 256>>>(h, gamma2, bias2, beta2, U02, s16, BB, TT, HH);

    // ---- layer 3 ----
    gemm_fp16x2<<<dim3(JJ / GBN, MM / GBM), 256, SMEMB>>>(s16, w3a, w3b, h, MM, JJ, HH, 0);
    colstats<<<JJ / 32, dim3(32, 16)>>>(h, MM, JJ);
    lif_scan<float><<<(BB * JJ + 255) / 256, 256>>>(h, gamma3, bias3, beta3, U03, out, BB, TT, JJ);
}

// round 5
// speedup vs baseline: 2.2489x; 1.0450x over previous
#include <cuda_runtime.h>
#include <cuda_fp16.h>
#include <math.h>
#include <stdint.h>

// Shapes fixed by dataset: B=32, T=1024, J=1024, H=2048
#define BB 32
#define TT 1024
#define JJ 1024
#define HH 2048
#define MM (BB*TT)   // 32768

// ---------------- scratch (device globals; no allocations allowed) ----------------
__device__ float  g_h [(size_t)MM * HH];      // pre-activation fp32
__device__ __half g_s16[(size_t)MM * HH];     // spikes fp16
__device__ __half g_x0[(size_t)MM * JJ];      // x hi
__device__ __half g_x1[(size_t)MM * JJ];      // x lo
__device__ __half g_w1a[(size_t)HH * JJ], g_w1b[(size_t)HH * JJ];
__device__ __half g_w2a[(size_t)HH * HH], g_w2b[(size_t)HH * HH];
__device__ __half g_w3a[(size_t)JJ * HH], g_w3b[(size_t)JJ * HH];
__device__ float  g_mu[HH], g_var[HH];

// ---------------- helpers ----------------
__device__ __forceinline__ void cpasync16(void* dst, const void* src) {
    unsigned sa = (unsigned)__cvta_generic_to_shared(dst);
    asm volatile("cp.async.cg.shared.global [%0], [%1], 16;\n" :: "r"(sa), "l"(src));
}
__device__ __forceinline__ void ldm4(uint32_t* r, const __half* p) {
    unsigned a = (unsigned)__cvta_generic_to_shared(p);
    asm volatile("ldmatrix.sync.aligned.m8n8.x4.shared.b16 {%0,%1,%2,%3}, [%4];"
                 : "=r"(r[0]), "=r"(r[1]), "=r"(r[2]), "=r"(r[3]) : "r"(a));
}
__device__ __forceinline__ void mma16816(float* c, const uint32_t* a, uint32_t b0, uint32_t b1) {
    asm volatile("mma.sync.aligned.m16n8k16.row.col.f32.f16.f16.f32 "
                 "{%0,%1,%2,%3},{%4,%5,%6,%7},{%8,%9},{%0,%1,%2,%3};"
                 : "+f"(c[0]), "+f"(c[1]), "+f"(c[2]), "+f"(c[3])
                 : "r"(a[0]), "r"(a[1]), "r"(a[2]), "r"(a[3]), "r"(b0), "r"(b1));
}

// ---------------- fp32 -> (hi, lo) fp16 split ----------------
__global__ void split_f32(const float* __restrict__ src,
                          __half* __restrict__ a, __half* __restrict__ b, size_t n)
{
    size_t i = (size_t)blockIdx.x * blockDim.x + threadIdx.x;
    if (i >= n) return;
    float v = src[i];
    __half hi = __float2half_rn(v);
    a[i] = hi;
    b[i] = __float2half_rn(v - __half2float(hi));
}

// ---------------- fp16 tensor-core GEMM: C[M,N] (+)= A[M,K] * (sum_b B_b)[N,K]^T ----
// CTA tile 128x128, k-tile 32, 3-stage cp.async pipeline, 8 warps (2x4), warp tile 64x32.
// smem row = 32 halves + 8 pad (80B) -> conflict-free ldmatrix.
#define TSH 40
#define ARRH (128*TSH)                 // halves per 128x32 array
#define ARRB (ARRH*2)                  // bytes

template<int NB>
__global__ __launch_bounds__(256, 2) void gemm_v2(
    const __half* __restrict__ A, const __half* __restrict__ B0, const __half* __restrict__ B1,
    float* __restrict__ C, int N, int K, int accum)
{
    constexpr int NARR = 1 + NB;
    constexpr uint32_t STAGEB = NARR * ARRB;

    extern __shared__ __half smem[];

    const int tid  = threadIdx.x;
    const int lane = tid & 31;
    const int warp = tid >> 5;
    const int wm   = warp >> 2;   // 0..1
    const int wn   = warp & 3;    // 0..3
    const int bm   = blockIdx.y * 128;
    const int bn   = blockIdx.x * 128;

    const __half* gbase[3];
    gbase[0] = A  + (size_t)bm * K;
    gbase[1] = B0 + (size_t)bn * K;
    if (NB == 2) gbase[2] = B1 + (size_t)bn * K;

    float acc[4][4][4];
#pragma unroll
    for (int i = 0; i < 4; i++)
#pragma unroll
        for (int j = 0; j < 4; j++)
#pragma unroll
            for (int k = 0; k < 4; k++) acc[i][j][k] = 0.0f;

    const int NK = K >> 5;   // k32 tiles

    auto load_stage = [&](int kt, int slot) {
        const int kb = kt << 5;
        char* sb = (char*)smem + (uint32_t)slot * STAGEB;
#pragma unroll
        for (int a = 0; a < NARR; a++) {
            const __half* g = gbase[a];
            char* sa = sb + a * ARRB;
#pragma unroll
            for (int c = tid; c < 512; c += 256) {
                int r = c >> 2, q = c & 3;
                cpasync16(sa + r * (TSH*2) + q * 16, g + (size_t)r * K + kb + q * 8);
            }
        }
        asm volatile("cp.async.commit_group;");
    };

    load_stage(0, 0);
    if (NK > 1) load_stage(1, 1);

    for (int kt = 0; kt < NK; kt++) {
        if (kt + 1 < NK) asm volatile("cp.async.wait_group 1;");
        else             asm volatile("cp.async.wait_group 0;");
        __syncthreads();

        if (kt + 2 < NK) load_stage(kt + 2, (kt + 2) % 3);

        const __half* sb = smem + (uint32_t)((kt % 3) * STAGEB / 2);
        const __half* tA  = sb;
        const __half* tB0 = sb + ARRH;
        const __half* tB1 = sb + 2 * ARRH;

#pragma unroll
        for (int k16 = 0; k16 < 32; k16 += 16) {
            uint32_t af[4][4];
            {
                int r  = wm * 64 + (lane & 7) + ((lane >> 3) & 1) * 8;
                int kc = k16 + (lane >> 4) * 8;
#pragma unroll
                for (int mt = 0; mt < 4; mt++)
                    ldm4(af[mt], tA + (r + mt * 16) * TSH + kc);
            }
#pragma unroll
            for (int p = 0; p < NB; p++) {
                const __half* tB = p ? tB1 : tB0;
                uint32_t bf[2][4];
                {
                    int r  = wn * 32 + (lane & 7) + (lane >> 4) * 8;
                    int kc = k16 + ((lane >> 3) & 1) * 8;
#pragma unroll
                    for (int g = 0; g < 2; g++)
                        ldm4(bf[g], tB + (r + g * 16) * TSH + kc);
                }
#pragma unroll
                for (int mt = 0; mt < 4; mt++)
#pragma unroll
                    for (int nt = 0; nt < 4; nt++)
                        mma16816(acc[mt][nt], af[mt],
                                 bf[nt >> 1][(nt & 1) * 2], bf[nt >> 1][(nt & 1) * 2 + 1]);
            }
        }
    }

    // epilogue
#pragma unroll
    for (int mt = 0; mt < 4; mt++) {
#pragma unroll
        for (int nt = 0; nt < 4; nt++) {
            int row = bm + wm * 64 + mt * 16 + (lane >> 2);
            int col = bn + wn * 32 + nt * 8 + (lane & 3) * 2;
            float2* p0 = (float2*)(C + (size_t)row * N + col);
            float2* p1 = (float2*)(C + (size_t)(row + 8) * N + col);
            float2 v0 = make_float2(acc[mt][nt][0], acc[mt][nt][1]);
            float2 v1 = make_float2(acc[mt][nt][2], acc[mt][nt][3]);
            if (accum) {
                float2 o0 = *p0, o1 = *p1;
                v0.x += o0.x; v0.y += o0.y; v1.x += o1.x; v1.y += o1.y;
            }
            *p0 = v0; *p1 = v1;
        }
    }
}

// ---------------- per-channel stats over 32768 rows (double accumulators) ----------------
__global__ void colstats(const float* __restrict__ h, int rows, int I)
{
    const int tx = threadIdx.x, ty = threadIdx.y;
    const int i = blockIdx.x * 32 + tx;

    double s = 0.0, q = 0.0;
    for (int r = ty; r < rows; r += 32) {
        double v = (double)h[(size_t)r * I + i];
        s += v; q += v * v;
    }
    __shared__ double sh_s[32][33], sh_q[32][33];
    sh_s[ty][tx] = s; sh_q[ty][tx] = q;
    __syncthreads();
    for (int off = 16; off > 0; off >>= 1) {
        if (ty < off) { sh_s[ty][tx] += sh_s[ty+off][tx]; sh_q[ty][tx] += sh_q[ty+off][tx]; }
        __syncthreads();
    }
    if (ty == 0) {
        double inv = 1.0 / (double)rows;
        double mu = sh_s[0][tx] * inv;
        g_mu[i]  = (float)mu;
        g_var[i] = (float)(sh_q[0][tx] * inv - mu * mu);
    }
}

// ---------------- BatchNorm + LIF scan ----------------
template <typename OutT>
__global__ void lif_scan(const float* __restrict__ h,
                         const float* __restrict__ gamma, const float* __restrict__ bias,
                         const float* __restrict__ betap, const float* __restrict__ U0,
                         OutT* __restrict__ S, int Bn, int T, int I)
{
    int idx = blockIdx.x * blockDim.x + threadIdx.x;
    if (idx >= Bn * I) return;
    int b = idx / I, i = idx - b * I;

    float m = g_mu[i];
    float rstd = (float)(1.0 / sqrt((double)g_var[i] + 1e-5));
    float g = gamma[i], bi = bias[i];
    float beta = (float)(1.0 / (1.0 + exp(-(double)betap[i])));
    float ombeta = 1.0f - beta;

    float U = U0[idx], Sv = 0.0f;
    const float* hp = h + (size_t)b * T * I + i;
    OutT* sp = S + (size_t)b * T * I + i;

    for (int t = 0; t < T; t++) {
        float x = ((hp[(size_t)t * I] - m) * rstd) * g + bi;
        U = beta * (U - Sv) + ombeta * x;
        Sv = (U >= 1.0f) ? 1.0f : 0.0f;
        sp[(size_t)t * I] = (OutT)Sv;
    }
}

// ---------------- driver ----------------
extern "C" void kernel_launch(void* const* d_in, const int* in_sizes, int n_in,
                              void* d_out, int out_size)
{
    const float* x      = (const float*)d_in[0];
    const float* W1     = (const float*)d_in[1];
    const float* beta1  = (const float*)d_in[2];
    const float* gamma1 = (const float*)d_in[3];
    const float* bias1  = (const float*)d_in[4];
    const float* U01    = (const float*)d_in[5];
    const float* W2     = (const float*)d_in[6];
    const float* beta2  = (const float*)d_in[7];
    const float* gamma2 = (const float*)d_in[8];
    const float* bias2  = (const float*)d_in[9];
    const float* U02    = (const float*)d_in[10];
    const float* W3     = (const float*)d_in[11];
    const float* beta3  = (const float*)d_in[12];
    const float* gamma3 = (const float*)d_in[13];
    const float* bias3  = (const float*)d_in[14];
    const float* U03    = (const float*)d_in[15];
    float* out = (float*)d_out;

    float *h; __half *s16, *x0, *x1, *w1a, *w1b, *w2a, *w2b, *w3a, *w3b;
    cudaGetSymbolAddress((void**)&h,   g_h);
    cudaGetSymbolAddress((void**)&s16, g_s16);
    cudaGetSymbolAddress((void**)&x0,  g_x0);
    cudaGetSymbolAddress((void**)&x1,  g_x1);
    cudaGetSymbolAddress((void**)&w1a, g_w1a);
    cudaGetSymbolAddress((void**)&w1b, g_w1b);
    cudaGetSymbolAddress((void**)&w2a, g_w2a);
    cudaGetSymbolAddress((void**)&w2b, g_w2b);
    cudaGetSymbolAddress((void**)&w3a, g_w3a);
    cudaGetSymbolAddress((void**)&w3b, g_w3b);

    const int SM2 = 3 * 3 * ARRB;   // 3 stages x (A,B0,B1) = 92160 B
    const int SM1 = 3 * 2 * ARRB;   // 3 stages x (A,B0)    = 61440 B
    cudaFuncSetAttribute(gemm_v2<2>, cudaFuncAttributeMaxDynamicSharedMemorySize, SM2);
    cudaFuncSetAttribute(gemm_v2<1>, cudaFuncAttributeMaxDynamicSharedMemorySize, SM1);

    // splits
    split_f32<<<(unsigned)(((size_t)MM * JJ + 255) / 256), 256>>>(x,  x0,  x1,  (size_t)MM * JJ);
    split_f32<<<(unsigned)(((size_t)HH * JJ + 255) / 256), 256>>>(W1, w1a, w1b, (size_t)HH * JJ);
    split_f32<<<(unsigned)(((size_t)HH * HH + 255) / 256), 256>>>(W2, w2a, w2b, (size_t)HH * HH);
    split_f32<<<(unsigned)(((size_t)JJ * HH + 255) / 256), 256>>>(W3, w3a, w3b, (size_t)JJ * HH);

    // ---- layer 1: h = x0@(W1a+W1b)^T + x1@W1a^T   (lo*lo term dropped) ----
    gemm_v2<2><<<dim3(HH / 128, MM / 128), 256, SM2>>>(x0, w1a, w1b, h, HH, JJ, 0);
    gemm_v2<1><<<dim3(HH / 128, MM / 128), 256, SM1>>>(x1, w1a, nullptr, h, HH, JJ, 1);
    colstats<<<HH / 32, dim3(32, 32)>>>(h, MM, HH);
    lif_scan<__half><<<(BB * HH + 255) / 256, 256>>>(h, gamma1, bias1, beta1, U01, s16, BB, TT, HH);

    // ---- layer 2 ----
    gemm_v2<2><<<dim3(HH / 128, MM / 128), 256, SM2>>>(s16, w2a, w2b, h, HH, HH, 0);
    colstats<<<HH / 32, dim3(32, 32)>>>(h, MM, HH);
    lif_scan<__half><<<(BB * HH + 255) / 256, 256>>>(h, gamma2, bias2, beta2, U02, s16, BB, TT, HH);

    // ---- layer 3 ----
    gemm_v2<2><<<dim3(JJ / 128, MM / 128), 256, SM1 <= SM2 ? SM2 : SM2>>>(s16, w3a, w3b, h, JJ, HH, 0);
    colstats<<<JJ / 32, dim3(32, 32)>>>(h, MM, JJ);
    lif_scan<float><<<(BB * JJ + 255) / 256, 256>>>(h, gamma3, bias3, beta3, U03, out, BB, TT, JJ);
}